// round 1
// baseline (speedup 1.0000x reference)
#include <cuda_runtime.h>
#include <cuda_bf16.h>
#include <math.h>

#define BB 4
#define LL 2048
#define DD 1024
#define HH 16
#define DH 64
#define NS 16
#define EE 16
#define FF 4096

// ---------------- scratch (device globals; no allocation allowed) ----------------
__device__ float g_kh  [BB*LL*DD];   // dispatch K heads
__device__ float g_vh  [BB*LL*DD];   // dispatch V heads
__device__ float g_qh1 [NS*DD];      // dispatch Q heads (batch-independent)
__device__ float g_att1[BB*NS*DD];   // dispatch attention output (pre-Wo)
__device__ float g_o   [BB*NS*DD];   // slots (residual stream)
__device__ float g_hn  [BB*NS*DD];   // layernormed slots
__device__ float g_ug  [BB*EE*FF];   // silu(u)*silu(g)
__device__ float g_qh2 [BB*LL*DD];   // combine Q heads
__device__ float g_kh2 [BB*NS*DD];
__device__ float g_vh2 [BB*NS*DD];
__device__ float g_att2[BB*LL*DD];   // combine attention output (pre-Wo)

// ---------------- generic SGEMM: C[M,N] = A[M,K] @ W[K,N] + bias[N] ----------------
// 128x128 tile, BK=8, 256 threads, 8x8 microtile. N,K multiples of 128 here.
__global__ __launch_bounds__(256, 2)
void gemm_bias(const float* __restrict__ A, const float* __restrict__ W,
               const float* __restrict__ bias, float* __restrict__ C,
               int M, int N, int K)
{
    __shared__ float As[8][128];
    __shared__ float Bs[8][128];
    const int tid  = threadIdx.x;
    const int row0 = blockIdx.y * 128;
    const int col0 = blockIdx.x * 128;
    const int tm = (tid >> 4) * 8;   // 0..120
    const int tn = (tid & 15) * 8;

    const int arow = tid >> 1;            // 0..127
    const int acol = (tid & 1) * 4;       // 0 or 4
    const int brow = tid >> 5;            // 0..7
    const int bcol = (tid & 31) * 4;      // 0..124

    float acc[8][8];
#pragma unroll
    for (int i = 0; i < 8; i++)
#pragma unroll
        for (int j = 0; j < 8; j++) acc[i][j] = 0.f;

    for (int k0 = 0; k0 < K; k0 += 8) {
        float4 av = make_float4(0.f, 0.f, 0.f, 0.f);
        if (row0 + arow < M)
            av = *(const float4*)&A[(size_t)(row0 + arow) * K + k0 + acol];
        As[acol + 0][arow] = av.x;
        As[acol + 1][arow] = av.y;
        As[acol + 2][arow] = av.z;
        As[acol + 3][arow] = av.w;

        float4 bv = *(const float4*)&W[(size_t)(k0 + brow) * N + col0 + bcol];
        *(float4*)&Bs[brow][bcol] = bv;
        __syncthreads();

#pragma unroll
        for (int kk = 0; kk < 8; kk++) {
            float4 a0 = *(const float4*)&As[kk][tm];
            float4 a1 = *(const float4*)&As[kk][tm + 4];
            float4 b0 = *(const float4*)&Bs[kk][tn];
            float4 b1 = *(const float4*)&Bs[kk][tn + 4];
            float af[8] = {a0.x, a0.y, a0.z, a0.w, a1.x, a1.y, a1.z, a1.w};
            float bf[8] = {b0.x, b0.y, b0.z, b0.w, b1.x, b1.y, b1.z, b1.w};
#pragma unroll
            for (int i = 0; i < 8; i++)
#pragma unroll
                for (int j = 0; j < 8; j++) acc[i][j] += af[i] * bf[j];
        }
        __syncthreads();
    }

#pragma unroll
    for (int i = 0; i < 8; i++) {
        int r = row0 + tm + i;
        if (r < M) {
#pragma unroll
            for (int j = 0; j < 8; j += 4) {
                float4 o;
                o.x = acc[i][j + 0] + bias[col0 + tn + j + 0];
                o.y = acc[i][j + 1] + bias[col0 + tn + j + 1];
                o.z = acc[i][j + 2] + bias[col0 + tn + j + 2];
                o.w = acc[i][j + 3] + bias[col0 + tn + j + 3];
                *(float4*)&C[(size_t)r * N + col0 + tn + j] = o;
            }
        }
    }
}

// ---------------- dispatch attention: slots attend to tokens ----------------
// grid (H, B), 256 threads. smem: q[NS*DH] + scores[NS*LL] + tile[128*65]
__global__ void dispatch_attn(const float* __restrict__ qh,  // [NS, D]
                              const float* __restrict__ kh,  // [B, L, D]
                              const float* __restrict__ vh,  // [B, L, D]
                              float* __restrict__ out)       // [B, NS, D]
{
    extern __shared__ float sm[];
    float* qsm  = sm;                    // NS*DH = 1024
    float* sc   = sm + NS * DH;          // NS*LL = 32768
    float* tile = sc + NS * LL;          // 128*65 = 8320 (padded rows)
    const int h = blockIdx.x;
    const int b = blockIdx.y;
    const int tid = threadIdx.x;
    const int TJ = 128;

    for (int i = tid; i < NS * DH; i += 256) {
        int s = i >> 6, d = i & 63;
        qsm[i] = qh[(size_t)s * DD + h * DH + d];
    }
    __syncthreads();

    for (int j0 = 0; j0 < LL; j0 += TJ) {
        for (int i = tid; i < TJ * DH; i += 256) {
            int jj = i >> 6, d = i & 63;
            tile[jj * 65 + d] = kh[((size_t)b * LL + j0 + jj) * DD + h * DH + d];
        }
        __syncthreads();
        for (int idx = tid; idx < NS * TJ; idx += 256) {
            int s = idx / TJ, jj = idx % TJ;
            float dot = 0.f;
#pragma unroll
            for (int d = 0; d < DH; d++) dot += qsm[s * DH + d] * tile[jj * 65 + d];
            sc[s * LL + j0 + jj] = dot * 0.125f;
        }
        __syncthreads();
    }

    // softmax: 16 threads per slot
    {
        int s = tid >> 4, lane = tid & 15;
        float mx = -1e30f;
        for (int j = lane; j < LL; j += 16) mx = fmaxf(mx, sc[s * LL + j]);
#pragma unroll
        for (int o = 8; o >= 1; o >>= 1) mx = fmaxf(mx, __shfl_xor_sync(0xffffffffu, mx, o));
        float sum = 0.f;
        for (int j = lane; j < LL; j += 16) {
            float e = __expf(sc[s * LL + j] - mx);
            sc[s * LL + j] = e;
            sum += e;
        }
#pragma unroll
        for (int o = 8; o >= 1; o >>= 1) sum += __shfl_xor_sync(0xffffffffu, sum, o);
        float inv = 1.f / sum;
        for (int j = lane; j < LL; j += 16) sc[s * LL + j] *= inv;
    }
    __syncthreads();

    float acc[4] = {0.f, 0.f, 0.f, 0.f};
    for (int j0 = 0; j0 < LL; j0 += TJ) {
        for (int i = tid; i < TJ * DH; i += 256) {
            int jj = i >> 6, d = i & 63;
            tile[jj * 65 + d] = vh[((size_t)b * LL + j0 + jj) * DD + h * DH + d];
        }
        __syncthreads();
#pragma unroll
        for (int k = 0; k < 4; k++) {
            int idx = tid + k * 256;
            int s = idx >> 6, d = idx & 63;
            float a = acc[k];
            for (int jj = 0; jj < TJ; jj++)
                a += sc[s * LL + j0 + jj] * tile[jj * 65 + d];
            acc[k] = a;
        }
        __syncthreads();
    }
#pragma unroll
    for (int k = 0; k < 4; k++) {
        int idx = tid + k * 256;
        int s = idx >> 6, d = idx & 63;
        out[((size_t)b * NS + s) * DD + h * DH + d] = acc[k];
    }
}

// o[b,s,:] += slot_query[s,:]
__global__ void add_slotq(float* __restrict__ o, const float* __restrict__ sq)
{
    int i = blockIdx.x * 256 + threadIdx.x;
    if (i < BB * NS * DD) o[i] += sq[i % (NS * DD)];
}

// ---------------- layernorm over D per (b,slot) ----------------
__global__ void ln_kernel(const float* __restrict__ inp, const float* __restrict__ gam,
                          const float* __restrict__ bet, float* __restrict__ outp)
{
    const int row = blockIdx.x;   // b*NS + s
    const int e = row & (NS - 1); // expert = slot (S=1)
    const float* xr = inp + (size_t)row * DD;
    __shared__ float r1[8], r2[8];
    float s1 = 0.f, s2 = 0.f;
    for (int d = threadIdx.x; d < DD; d += 256) {
        float v = xr[d];
        s1 += v;
        s2 += v * v;
    }
#pragma unroll
    for (int o = 16; o; o >>= 1) {
        s1 += __shfl_xor_sync(0xffffffffu, s1, o);
        s2 += __shfl_xor_sync(0xffffffffu, s2, o);
    }
    int wid = threadIdx.x >> 5, lane = threadIdx.x & 31;
    if (!lane) { r1[wid] = s1; r2[wid] = s2; }
    __syncthreads();
    if (threadIdx.x < 32) {
        s1 = (lane < 8) ? r1[lane] : 0.f;
        s2 = (lane < 8) ? r2[lane] : 0.f;
#pragma unroll
        for (int o = 4; o; o >>= 1) {
            s1 += __shfl_xor_sync(0xffffffffu, s1, o);
            s2 += __shfl_xor_sync(0xffffffffu, s2, o);
        }
        if (!lane) { r1[0] = s1; r2[0] = s2; }
    }
    __syncthreads();
    float mu  = r1[0] * (1.f / DD);
    float var = r2[0] * (1.f / DD) - mu * mu;
    float inv = rsqrtf(var + 1e-5f);
    for (int d = threadIdx.x; d < DD; d += 256)
        outp[(size_t)row * DD + d] = (xr[d] - mu) * inv * gam[(size_t)e * DD + d] + bet[(size_t)e * DD + d];
}

__device__ __forceinline__ float silu_f(float x) { return x / (1.f + __expf(-x)); }

// ---------------- expert up/gate: ug[b,e,f] = silu(h@W1+b1)*silu(h@Wg+bg) ----------------
// grid (F/256, E), 256 threads
__global__ void expert_ug(const float* __restrict__ hn,
                          const float* __restrict__ W1, const float* __restrict__ b1,
                          const float* __restrict__ Wg, const float* __restrict__ bg,
                          float* __restrict__ ug)
{
    const int e = blockIdx.y;
    const int f = blockIdx.x * 256 + threadIdx.x;
    __shared__ float hs[BB][DD];
    for (int i = threadIdx.x; i < BB * DD; i += 256) {
        int b = i >> 10, d = i & 1023;
        hs[b][d] = hn[((size_t)b * NS + e) * DD + d];
    }
    __syncthreads();

    const float* w1 = W1 + (size_t)e * DD * FF + f;
    const float* wg = Wg + (size_t)e * DD * FF + f;
    float au[BB] = {0.f, 0.f, 0.f, 0.f};
    float ag[BB] = {0.f, 0.f, 0.f, 0.f};
#pragma unroll 8
    for (int d = 0; d < DD; d++) {
        float w1v = __ldg(&w1[(size_t)d * FF]);
        float wgv = __ldg(&wg[(size_t)d * FF]);
#pragma unroll
        for (int b = 0; b < BB; b++) {
            float hv = hs[b][d];
            au[b] += hv * w1v;
            ag[b] += hv * wgv;
        }
    }
    float bu = b1[(size_t)e * FF + f];
    float bv = bg[(size_t)e * FF + f];
#pragma unroll
    for (int b = 0; b < BB; b++)
        ug[((size_t)b * EE + e) * FF + f] = silu_f(au[b] + bu) * silu_f(ag[b] + bv);
}

// ---------------- expert down: o[b,slot e,d] += ug@W2 + b2 ----------------
// grid (D/64, E), 64 threads, dynamic smem BB*FF floats (64KB)
__global__ void expert_w2(const float* __restrict__ ug, const float* __restrict__ W2,
                          const float* __restrict__ b2, float* __restrict__ o)
{
    extern __shared__ float as2[];   // [BB][FF]
    const int e = blockIdx.y;
    const int d = blockIdx.x * 64 + threadIdx.x;
    for (int i = threadIdx.x; i < BB * FF; i += 64) {
        int b = i >> 12, f = i & 4095;
        as2[b * FF + f] = ug[((size_t)b * EE + e) * FF + f];
    }
    __syncthreads();
    const float* w = W2 + (size_t)e * FF * DD + d;
    float acc[BB] = {0.f, 0.f, 0.f, 0.f};
#pragma unroll 8
    for (int f = 0; f < FF; f++) {
        float wv = __ldg(&w[(size_t)f * DD]);
#pragma unroll
        for (int b = 0; b < BB; b++) acc[b] += as2[b * FF + f] * wv;
    }
    float bb = b2[(size_t)e * DD + d];
#pragma unroll
    for (int b = 0; b < BB; b++)
        o[((size_t)b * NS + e) * DD + d] += acc[b] + bb;
}

// ---------------- combine attention: tokens attend to slots ----------------
// grid (L/16, B), 256 threads: thread = (token-in-chunk, head)
// smem: q/k/v staged with per-head pitch 65 (bank-conflict-free across heads)
__global__ void combine_attn(const float* __restrict__ qh,  // [B, L, D]
                             const float* __restrict__ kh,  // [B, NS, D]
                             const float* __restrict__ vh,  // [B, NS, D]
                             float* __restrict__ out)       // [B, L, D]
{
    extern __shared__ float sm[];
    const int PITCH = HH * 65; // 1040 floats per row (token or slot)
    float* qsm = sm;               // 16 * 1040
    float* ksm = sm + 16 * PITCH;  // 16 * 1040
    float* vsm = sm + 32 * PITCH;  // 16 * 1040
    const int b  = blockIdx.y;
    const int t0 = blockIdx.x * 16;
    const int tid = threadIdx.x;

    for (int i = tid; i < NS * DD; i += 256) {
        int r = i >> 10, hd = i & 1023;
        int h = hd >> 6, d = hd & 63;
        int sw = r * PITCH + h * 65 + d;
        ksm[sw] = kh[(size_t)b * NS * DD + i];
        vsm[sw] = vh[(size_t)b * NS * DD + i];
        qsm[sw] = qh[((size_t)b * LL + t0) * DD + i];
    }
    __syncthreads();

    const int tt = tid >> 4;
    const int h  = tid & 15;

    float qreg[DH];
#pragma unroll
    for (int d = 0; d < DH; d++) qreg[d] = qsm[tt * PITCH + h * 65 + d];

    float sco[NS];
    float mx = -1e30f;
#pragma unroll
    for (int s = 0; s < NS; s++) {
        const float* kp = &ksm[s * PITCH + h * 65];
        float dot = 0.f;
#pragma unroll
        for (int d = 0; d < DH; d++) dot += qreg[d] * kp[d];
        dot *= 0.125f;
        sco[s] = dot;
        mx = fmaxf(mx, dot);
    }
    float sum = 0.f;
#pragma unroll
    for (int s = 0; s < NS; s++) { sco[s] = __expf(sco[s] - mx); sum += sco[s]; }
    float inv = 1.f / sum;

    float ov[DH];
#pragma unroll
    for (int d = 0; d < DH; d++) ov[d] = 0.f;
#pragma unroll
    for (int s = 0; s < NS; s++) {
        float p = sco[s] * inv;
        const float* vp = &vsm[s * PITCH + h * 65];
#pragma unroll
        for (int d = 0; d < DH; d++) ov[d] += p * vp[d];
    }
    __syncthreads();
#pragma unroll
    for (int d = 0; d < DH; d++) qsm[tt * PITCH + h * 65 + d] = ov[d];
    __syncthreads();
    for (int i = tid; i < NS * DD; i += 256) {
        int r = i >> 10, hd = i & 1023;
        int hh = hd >> 6, d = hd & 63;
        out[((size_t)b * LL + t0) * DD + i] = qsm[r * PITCH + hh * 65 + d];
    }
}

// ---------------- host launch ----------------
extern "C" void kernel_launch(void* const* d_in, const int* in_sizes, int n_in,
                              void* d_out, int out_size)
{
    const float* x    = (const float*)d_in[0];
    const float* sq   = (const float*)d_in[1];
    const float* dWq  = (const float*)d_in[2];
    const float* dWk  = (const float*)d_in[3];
    const float* dWv  = (const float*)d_in[4];
    const float* dWo  = (const float*)d_in[5];
    const float* dbq  = (const float*)d_in[6];
    const float* dbk  = (const float*)d_in[7];
    const float* dbv  = (const float*)d_in[8];
    const float* dbo  = (const float*)d_in[9];
    const float* cWq  = (const float*)d_in[10];
    const float* cWk  = (const float*)d_in[11];
    const float* cWv  = (const float*)d_in[12];
    const float* cWo  = (const float*)d_in[13];
    const float* cbq  = (const float*)d_in[14];
    const float* cbk  = (const float*)d_in[15];
    const float* cbv  = (const float*)d_in[16];
    const float* cbo  = (const float*)d_in[17];
    const float* elng = (const float*)d_in[18];
    const float* elnb = (const float*)d_in[19];
    const float* eW1  = (const float*)d_in[20];
    const float* eb1  = (const float*)d_in[21];
    const float* eWg  = (const float*)d_in[22];
    const float* ebg  = (const float*)d_in[23];
    const float* eW2  = (const float*)d_in[24];
    const float* eb2  = (const float*)d_in[25];
    float* out = (float*)d_out;

    float *kh, *vh, *qh1, *att1, *o, *hn, *ug, *qh2, *kh2, *vh2, *att2;
    cudaGetSymbolAddress((void**)&kh,   g_kh);
    cudaGetSymbolAddress((void**)&vh,   g_vh);
    cudaGetSymbolAddress((void**)&qh1,  g_qh1);
    cudaGetSymbolAddress((void**)&att1, g_att1);
    cudaGetSymbolAddress((void**)&o,    g_o);
    cudaGetSymbolAddress((void**)&hn,   g_hn);
    cudaGetSymbolAddress((void**)&ug,   g_ug);
    cudaGetSymbolAddress((void**)&qh2,  g_qh2);
    cudaGetSymbolAddress((void**)&kh2,  g_kh2);
    cudaGetSymbolAddress((void**)&vh2,  g_vh2);
    cudaGetSymbolAddress((void**)&att2, g_att2);

    const int SMEM_DISP = (NS * DH + NS * LL + 128 * 65) * 4;  // 168448 B
    const int SMEM_COMB = 3 * 16 * (HH * 65) * 4;              // 199680 B
    const int SMEM_W2   = BB * FF * 4;                          // 65536 B
    cudaFuncSetAttribute(dispatch_attn, cudaFuncAttributeMaxDynamicSharedMemorySize, SMEM_DISP);
    cudaFuncSetAttribute(combine_attn,  cudaFuncAttributeMaxDynamicSharedMemorySize, SMEM_COMB);
    cudaFuncSetAttribute(expert_w2,     cudaFuncAttributeMaxDynamicSharedMemorySize, SMEM_W2);

    dim3 gBig(DD / 128, (BB * LL) / 128);   // (8, 64)
    dim3 gTiny(DD / 128, 1);                // (8, 1)

    // dispatch K/V/Q projections
    gemm_bias<<<gBig, 256>>>(x, dWk, dbk, kh, BB * LL, DD, DD);
    gemm_bias<<<gBig, 256>>>(x, dWv, dbv, vh, BB * LL, DD, DD);
    gemm_bias<<<gTiny, 256>>>(sq, dWq, dbq, qh1, NS, DD, DD);

    // dispatch attention + output projection + residual
    dispatch_attn<<<dim3(HH, BB), 256, SMEM_DISP>>>(qh1, kh, vh, att1);
    gemm_bias<<<gTiny, 256>>>(att1, dWo, dbo, o, BB * NS, DD, DD);
    add_slotq<<<(BB * NS * DD) / 256, 256>>>(o, sq);

    // experts
    ln_kernel<<<BB * NS, 256>>>(o, elng, elnb, hn);
    expert_ug<<<dim3(FF / 256, EE), 256>>>(hn, eW1, eb1, eWg, ebg, ug);
    expert_w2<<<dim3(DD / 64, EE), 64, SMEM_W2>>>(ug, eW2, eb2, o);

    // combine projections
    gemm_bias<<<gBig, 256>>>(x, cWq, cbq, qh2, BB * LL, DD, DD);
    gemm_bias<<<gTiny, 256>>>(o, cWk, cbk, kh2, BB * NS, DD, DD);
    gemm_bias<<<gTiny, 256>>>(o, cWv, cbv, vh2, BB * NS, DD, DD);

    // combine attention + final projection -> out
    combine_attn<<<dim3(LL / 16, BB), 256, SMEM_COMB>>>(qh2, kh2, vh2, att2);
    gemm_bias<<<gBig, 256>>>(att2, cWo, cbo, out, BB * LL, DD, DD);
}

// round 2
// speedup vs baseline: 3.5347x; 3.5347x over previous
#include <cuda_runtime.h>
#include <cuda_bf16.h>
#include <math.h>

#define BB 4
#define LL 2048
#define DD 1024
#define HH 16
#define DH 64
#define NS 16
#define EE 16
#define FF 4096

// ---------------- scratch ----------------
__device__ float g_kh  [BB*LL*DD];
__device__ float g_vh  [BB*LL*DD];
__device__ float g_qh1 [NS*DD];
__device__ float g_att1[BB*NS*DD];
__device__ float g_o   [BB*NS*DD];
__device__ float g_hn  [BB*NS*DD];
__device__ float g_ug  [BB*EE*FF];
__device__ float g_qh2 [BB*LL*DD];
__device__ float g_kh2 [BB*NS*DD];
__device__ float g_vh2 [BB*NS*DD];
__device__ float g_att2[BB*LL*DD];
__device__ float g_sc  [BB*HH*NS*LL];    // dispatch scores (8MB)
__device__ float g_part[16*BB*NS*DD];    // AV split-J partials (4MB)
__device__ float g_skp [8*64*DD];        // skinny gemm split-K partials (2MB)
__device__ float g_w2p [8*BB*EE*DD];     // expert W2 split-F partials (2MB)

__device__ __forceinline__ unsigned f2tf32(float x) {
    unsigned y;
    asm("cvt.rna.tf32.f32 %0, %1;" : "=r"(y) : "f"(x));
    return y;
}

// ======================= TF32 tensor-core GEMM =======================
// C[M,N] = A[M,K] @ W[K,N] + bias[N].  M%128==0, N%128==0, K%32==0.
// 128x128x32 block tile, 256 threads (8 warps, 2x4), warp tile 64x32.
__global__ __launch_bounds__(256, 2)
void gemm_tf32(const float* __restrict__ A, const float* __restrict__ W,
               const float* __restrict__ bias, float* __restrict__ C,
               int M, int N, int K)
{
    __shared__ unsigned As[128][36];  // [m][k] tf32 bits, pitch 36 (frag-load conflict-free)
    __shared__ unsigned Bs[32][136];  // [k][n], pitch 136 (frag-load conflict-free)

    const int tid  = threadIdx.x;
    const int wid  = tid >> 5;
    const int lane = tid & 31;
    const int g    = lane >> 2;    // groupID 0..7
    const int tig  = lane & 3;     // thread-in-group 0..3
    const int wm0  = (wid >> 2) * 64;   // warp m offset (0/64)
    const int wn0  = (wid & 3) * 32;    // warp n offset (0/32/64/96)
    const int row0 = blockIdx.y * 128;
    const int col0 = blockIdx.x * 128;

    const int am  = tid >> 3;        // 0..31 (+32 per pass)
    const int ak  = (tid & 7) * 4;   // 0..28
    const int bkk = tid >> 5;        // 0..7 (+8 per pass... uses 4 passes of 8 k)
    const int bn  = (tid & 31) * 4;

    float acc[4][4][4];
#pragma unroll
    for (int i = 0; i < 4; i++)
#pragma unroll
        for (int j = 0; j < 4; j++)
#pragma unroll
            for (int c = 0; c < 4; c++) acc[i][j][c] = 0.f;

    for (int k0 = 0; k0 < K; k0 += 32) {
#pragma unroll
        for (int p = 0; p < 4; p++) {
            int m = am + p * 32;
            float4 av = *(const float4*)&A[(size_t)(row0 + m) * K + k0 + ak];
            As[m][ak + 0] = f2tf32(av.x);
            As[m][ak + 1] = f2tf32(av.y);
            As[m][ak + 2] = f2tf32(av.z);
            As[m][ak + 3] = f2tf32(av.w);

            int kb = bkk + p * 8;
            float4 bv = *(const float4*)&W[(size_t)(k0 + kb) * N + col0 + bn];
            Bs[kb][bn + 0] = f2tf32(bv.x);
            Bs[kb][bn + 1] = f2tf32(bv.y);
            Bs[kb][bn + 2] = f2tf32(bv.z);
            Bs[kb][bn + 3] = f2tf32(bv.w);
        }
        __syncthreads();

#pragma unroll
        for (int kk = 0; kk < 4; kk++) {
            unsigned af[4][4];
#pragma unroll
            for (int mt = 0; mt < 4; mt++) {
                int mb = wm0 + mt * 16;
                af[mt][0] = As[mb + g    ][kk * 8 + tig];
                af[mt][1] = As[mb + 8 + g][kk * 8 + tig];
                af[mt][2] = As[mb + g    ][kk * 8 + tig + 4];
                af[mt][3] = As[mb + 8 + g][kk * 8 + tig + 4];
            }
            unsigned bf[4][2];
#pragma unroll
            for (int nt = 0; nt < 4; nt++) {
                bf[nt][0] = Bs[kk * 8 + tig    ][wn0 + nt * 8 + g];
                bf[nt][1] = Bs[kk * 8 + tig + 4][wn0 + nt * 8 + g];
            }
#pragma unroll
            for (int mt = 0; mt < 4; mt++)
#pragma unroll
                for (int nt = 0; nt < 4; nt++) {
                    asm volatile(
                        "mma.sync.aligned.m16n8k8.row.col.f32.tf32.tf32.f32 "
                        "{%0,%1,%2,%3}, {%4,%5,%6,%7}, {%8,%9}, {%0,%1,%2,%3};\n"
                        : "+f"(acc[mt][nt][0]), "+f"(acc[mt][nt][1]),
                          "+f"(acc[mt][nt][2]), "+f"(acc[mt][nt][3])
                        : "r"(af[mt][0]), "r"(af[mt][1]), "r"(af[mt][2]), "r"(af[mt][3]),
                          "r"(bf[nt][0]), "r"(bf[nt][1]));
                }
        }
        __syncthreads();
    }

#pragma unroll
    for (int mt = 0; mt < 4; mt++) {
#pragma unroll
        for (int nt = 0; nt < 4; nt++) {
            int r = row0 + wm0 + mt * 16 + g;
            int c = col0 + wn0 + nt * 8 + tig * 2;
            float b0v = bias[c], b1v = bias[c + 1];
            float2 v0 = make_float2(acc[mt][nt][0] + b0v, acc[mt][nt][1] + b1v);
            float2 v1 = make_float2(acc[mt][nt][2] + b0v, acc[mt][nt][3] + b1v);
            *(float2*)&C[(size_t)r * N + c] = v0;
            *(float2*)&C[(size_t)(r + 8) * N + c] = v1;
        }
    }
}

// ======================= skinny split-K GEMM (M<=64) =======================
// part[ks][m][N] = A[m, ks*128 : +128] @ W[...]
template<int M>
__global__ void gemm_skinny(const float* __restrict__ A, const float* __restrict__ W,
                            float* __restrict__ part, int N, int K)
{
    __shared__ float As[64][132];
    const int tid = threadIdx.x;
    const int ks = blockIdx.y;
    const int n  = blockIdx.x * 64 + (tid & 63);
    const int mg = tid >> 6;  // 0..3
    const int k0 = ks * 128;

    for (int idx = tid; idx < M * 32; idx += 256) {
        int m = idx >> 5, c4 = (idx & 31) * 4;
        *(float4*)&As[m][c4] = *(const float4*)&A[(size_t)m * K + k0 + c4];
    }
    __syncthreads();

    const int MR = M / 4;
    float acc[MR];
#pragma unroll
    for (int r = 0; r < MR; r++) acc[r] = 0.f;

#pragma unroll 4
    for (int k = 0; k < 128; k++) {
        float wv = __ldg(&W[(size_t)(k0 + k) * N + n]);
#pragma unroll
        for (int r = 0; r < MR; r++) acc[r] += As[mg + 4 * r][k] * wv;
    }
#pragma unroll
    for (int r = 0; r < MR; r++)
        part[((size_t)ks * 64 + mg + 4 * r) * N + n] = acc[r];
}

__global__ void skinny_reduce(const float* __restrict__ part, const float* __restrict__ bias,
                              float* __restrict__ C, int M, int N)
{
    int i = blockIdx.x * 256 + threadIdx.x;
    if (i < M * N) {
        int n = i & (N - 1);
        int m = i / N;
        float s = bias[n];
#pragma unroll
        for (int z = 0; z < 8; z++) s += part[((size_t)z * 64 + m) * N + n];
        C[i] = s;
    }
}

// ======================= dispatch attention (4 phases) =======================
// phase 1: scores[b,h,s,j]
__global__ void disp_scores(const float* __restrict__ qh, const float* __restrict__ kh,
                            float* __restrict__ sc)
{
    __shared__ float q[16][64];
    __shared__ float kt[128][65];
    const int j0 = blockIdx.x * 128;
    const int h  = blockIdx.y;
    const int b  = blockIdx.z;
    const int tid = threadIdx.x;

    for (int i = tid; i < NS * DH; i += 256) {
        int s = i >> 6, d = i & 63;
        q[s][d] = qh[(size_t)s * DD + h * DH + d];
    }
#pragma unroll
    for (int p = 0; p < 8; p++) {
        int idx = tid + p * 256;          // 0..2047 float4s
        int jj = idx >> 4, d4 = (idx & 15) * 4;
        float4 v = *(const float4*)&kh[((size_t)b * LL + j0 + jj) * DD + h * DH + d4];
        kt[jj][d4 + 0] = v.x; kt[jj][d4 + 1] = v.y;
        kt[jj][d4 + 2] = v.z; kt[jj][d4 + 3] = v.w;
    }
    __syncthreads();

#pragma unroll
    for (int p = 0; p < 8; p++) {
        int idx = tid + p * 256;
        int s = idx >> 7, jj = idx & 127;
        float dot = 0.f;
#pragma unroll
        for (int d = 0; d < DH; d++) dot += q[s][d] * kt[jj][d];
        sc[(((size_t)b * HH + h) * NS + s) * LL + j0 + jj] = dot * 0.125f;
    }
}

// phase 2: softmax over j (one block per (b,h,s) row)
__global__ void disp_softmax(float* __restrict__ sc)
{
    __shared__ float red[9];
    const int tid = threadIdx.x;
    float* r = sc + (size_t)blockIdx.x * LL;
    float v[8];
    float mx = -1e30f;
#pragma unroll
    for (int i = 0; i < 8; i++) { v[i] = r[tid + i * 256]; mx = fmaxf(mx, v[i]); }
#pragma unroll
    for (int o = 16; o; o >>= 1) mx = fmaxf(mx, __shfl_xor_sync(0xffffffffu, mx, o));
    int wd = tid >> 5, ln = tid & 31;
    if (!ln) red[wd] = mx;
    __syncthreads();
    if (tid < 32) {
        mx = (ln < 8) ? red[ln] : -1e30f;
#pragma unroll
        for (int o = 4; o; o >>= 1) mx = fmaxf(mx, __shfl_xor_sync(0xffffffffu, mx, o));
        if (!ln) red[8] = mx;
    }
    __syncthreads();
    mx = red[8];
    float sum = 0.f;
#pragma unroll
    for (int i = 0; i < 8; i++) { v[i] = __expf(v[i] - mx); sum += v[i]; }
#pragma unroll
    for (int o = 16; o; o >>= 1) sum += __shfl_xor_sync(0xffffffffu, sum, o);
    __syncthreads();
    if (!ln) red[wd] = sum;
    __syncthreads();
    if (tid < 32) {
        sum = (ln < 8) ? red[ln] : 0.f;
#pragma unroll
        for (int o = 4; o; o >>= 1) sum += __shfl_xor_sync(0xffffffffu, sum, o);
        if (!ln) red[8] = sum;
    }
    __syncthreads();
    float inv = 1.f / red[8];
#pragma unroll
    for (int i = 0; i < 8; i++) r[tid + i * 256] = v[i] * inv;
}

// phase 3: partial AV over 128-token chunks
__global__ void disp_av(const float* __restrict__ sc, const float* __restrict__ vh,
                        float* __restrict__ part)
{
    __shared__ float p[16][132];
    __shared__ float vt[128][65];
    const int h = blockIdx.x, b = blockIdx.y, jz = blockIdx.z;
    const int j0 = jz * 128;
    const int tid = threadIdx.x;

#pragma unroll
    for (int q = 0; q < 2; q++) {
        int idx = tid + q * 256;   // 0..511 float4s (16 rows x 32)
        int s = idx >> 5, j4 = (idx & 31) * 4;
        float4 v = *(const float4*)&sc[(((size_t)b * HH + h) * NS + s) * LL + j0 + j4];
        *(float4*)&p[s][j4] = v;
    }
#pragma unroll
    for (int q = 0; q < 8; q++) {
        int idx = tid + q * 256;
        int jj = idx >> 4, d4 = (idx & 15) * 4;
        float4 v = *(const float4*)&vh[((size_t)b * LL + j0 + jj) * DD + h * DH + d4];
        vt[jj][d4 + 0] = v.x; vt[jj][d4 + 1] = v.y;
        vt[jj][d4 + 2] = v.z; vt[jj][d4 + 3] = v.w;
    }
    __syncthreads();

    float acc[4] = {0.f, 0.f, 0.f, 0.f};
#pragma unroll 4
    for (int jj = 0; jj < 128; jj++) {
#pragma unroll
        for (int k = 0; k < 4; k++) {
            int idx = tid + k * 256;
            int s = idx >> 6, d = idx & 63;
            acc[k] += p[s][jj] * vt[jj][d];
        }
    }
#pragma unroll
    for (int k = 0; k < 4; k++) {
        int idx = tid + k * 256;
        int s = idx >> 6, d = idx & 63;
        part[(size_t)jz * (BB * NS * DD) + ((size_t)b * NS + s) * DD + h * DH + d] = acc[k];
    }
}

// phase 4: sum 16 partials
__global__ void disp_reduce(const float* __restrict__ part, float* __restrict__ att1)
{
    int i = blockIdx.x * 256 + threadIdx.x;
    float s = 0.f;
#pragma unroll
    for (int z = 0; z < 16; z++) s += part[(size_t)z * (BB * NS * DD) + i];
    att1[i] = s;
}

// o[b,s,:] += slot_query[s,:]
__global__ void add_slotq(float* __restrict__ o, const float* __restrict__ sq)
{
    int i = blockIdx.x * 256 + threadIdx.x;
    if (i < BB * NS * DD) o[i] += sq[i % (NS * DD)];
}

// ---------------- layernorm over D per (b,slot) ----------------
__global__ void ln_kernel(const float* __restrict__ inp, const float* __restrict__ gam,
                          const float* __restrict__ bet, float* __restrict__ outp)
{
    const int row = blockIdx.x;
    const int e = row & (NS - 1);
    const float* xr = inp + (size_t)row * DD;
    __shared__ float r1[8], r2[8];
    float s1 = 0.f, s2 = 0.f;
    for (int d = threadIdx.x; d < DD; d += 256) {
        float v = xr[d];
        s1 += v; s2 += v * v;
    }
#pragma unroll
    for (int o = 16; o; o >>= 1) {
        s1 += __shfl_xor_sync(0xffffffffu, s1, o);
        s2 += __shfl_xor_sync(0xffffffffu, s2, o);
    }
    int wid = threadIdx.x >> 5, lane = threadIdx.x & 31;
    if (!lane) { r1[wid] = s1; r2[wid] = s2; }
    __syncthreads();
    if (threadIdx.x < 32) {
        s1 = (lane < 8) ? r1[lane] : 0.f;
        s2 = (lane < 8) ? r2[lane] : 0.f;
#pragma unroll
        for (int o = 4; o; o >>= 1) {
            s1 += __shfl_xor_sync(0xffffffffu, s1, o);
            s2 += __shfl_xor_sync(0xffffffffu, s2, o);
        }
        if (!lane) { r1[0] = s1; r2[0] = s2; }
    }
    __syncthreads();
    float mu  = r1[0] * (1.f / DD);
    float var = r2[0] * (1.f / DD) - mu * mu;
    float inv = rsqrtf(var + 1e-5f);
    for (int d = threadIdx.x; d < DD; d += 256)
        outp[(size_t)row * DD + d] = (xr[d] - mu) * inv * gam[(size_t)e * DD + d] + bet[(size_t)e * DD + d];
}

__device__ __forceinline__ float silu_f(float x) { return x / (1.f + __expf(-x)); }

// ---------------- expert up/gate ----------------
__global__ void expert_ug(const float* __restrict__ hn,
                          const float* __restrict__ W1, const float* __restrict__ b1,
                          const float* __restrict__ Wg, const float* __restrict__ bg,
                          float* __restrict__ ug)
{
    const int e = blockIdx.y;
    const int f = blockIdx.x * 128 + threadIdx.x;
    __shared__ float hs[BB][DD];
    for (int i = threadIdx.x; i < BB * DD; i += 128) {
        int b = i >> 10, d = i & 1023;
        hs[b][d] = hn[((size_t)b * NS + e) * DD + d];
    }
    __syncthreads();

    const float* w1 = W1 + (size_t)e * DD * FF + f;
    const float* wg = Wg + (size_t)e * DD * FF + f;
    float au[BB] = {0.f, 0.f, 0.f, 0.f};
    float ag[BB] = {0.f, 0.f, 0.f, 0.f};
#pragma unroll 8
    for (int d = 0; d < DD; d++) {
        float w1v = __ldg(&w1[(size_t)d * FF]);
        float wgv = __ldg(&wg[(size_t)d * FF]);
#pragma unroll
        for (int b = 0; b < BB; b++) {
            float hv = hs[b][d];
            au[b] += hv * w1v;
            ag[b] += hv * wgv;
        }
    }
    float bu = b1[(size_t)e * FF + f];
    float bv = bg[(size_t)e * FF + f];
#pragma unroll
    for (int b = 0; b < BB; b++)
        ug[((size_t)b * EE + e) * FF + f] = silu_f(au[b] + bu) * silu_f(ag[b] + bv);
}

// ---------------- expert down: split-F partials ----------------
__global__ void expert_w2p(const float* __restrict__ ug, const float* __restrict__ W2,
                           float* __restrict__ part)
{
    __shared__ float us[BB][512];
    const int e = blockIdx.y, fz = blockIdx.z;
    const int d = blockIdx.x * 128 + threadIdx.x;
    for (int i = threadIdx.x; i < BB * 512; i += 128) {
        int b = i >> 9, f = i & 511;
        us[b][f] = ug[((size_t)b * EE + e) * FF + fz * 512 + f];
    }
    __syncthreads();
    const float* w = W2 + ((size_t)e * FF + fz * 512) * DD + d;
    float acc[BB] = {0.f, 0.f, 0.f, 0.f};
#pragma unroll 4
    for (int f = 0; f < 512; f++) {
        float wv = __ldg(&w[(size_t)f * DD]);
#pragma unroll
        for (int b = 0; b < BB; b++) acc[b] += us[b][f] * wv;
    }
#pragma unroll
    for (int b = 0; b < BB; b++)
        part[(size_t)fz * (BB * EE * DD) + ((size_t)b * EE + e) * DD + d] = acc[b];
}

__global__ void w2_reduce(const float* __restrict__ part, const float* __restrict__ b2,
                          float* __restrict__ o)
{
    int i = blockIdx.x * 256 + threadIdx.x;   // BB*EE*DD
    int d = i & 1023;
    int e = (i >> 10) & 15;
    float s = b2[(size_t)e * DD + d];
#pragma unroll
    for (int z = 0; z < 8; z++) s += part[(size_t)z * (BB * EE * DD) + i];
    o[i] += s;
}

// ---------------- combine attention ----------------
__global__ void combine_attn(const float* __restrict__ qh, const float* __restrict__ kh,
                             const float* __restrict__ vh, float* __restrict__ out)
{
    extern __shared__ float sm[];
    const int PITCH = HH * 65;
    float* qsm = sm;
    float* ksm = sm + 16 * PITCH;
    float* vsm = sm + 32 * PITCH;
    const int b  = blockIdx.y;
    const int t0 = blockIdx.x * 16;
    const int tid = threadIdx.x;

    for (int i = tid; i < NS * DD; i += 256) {
        int r = i >> 10, hd = i & 1023;
        int h = hd >> 6, d = hd & 63;
        int sw = r * PITCH + h * 65 + d;
        ksm[sw] = kh[(size_t)b * NS * DD + i];
        vsm[sw] = vh[(size_t)b * NS * DD + i];
        qsm[sw] = qh[((size_t)b * LL + t0) * DD + i];
    }
    __syncthreads();

    const int tt = tid >> 4;
    const int h  = tid & 15;

    float qreg[DH];
#pragma unroll
    for (int d = 0; d < DH; d++) qreg[d] = qsm[tt * PITCH + h * 65 + d];

    float sco[NS];
    float mx = -1e30f;
#pragma unroll
    for (int s = 0; s < NS; s++) {
        const float* kp = &ksm[s * PITCH + h * 65];
        float dot = 0.f;
#pragma unroll
        for (int d = 0; d < DH; d++) dot += qreg[d] * kp[d];
        dot *= 0.125f;
        sco[s] = dot;
        mx = fmaxf(mx, dot);
    }
    float sum = 0.f;
#pragma unroll
    for (int s = 0; s < NS; s++) { sco[s] = __expf(sco[s] - mx); sum += sco[s]; }
    float inv = 1.f / sum;

    float ov[DH];
#pragma unroll
    for (int d = 0; d < DH; d++) ov[d] = 0.f;
#pragma unroll
    for (int s = 0; s < NS; s++) {
        float pr = sco[s] * inv;
        const float* vp = &vsm[s * PITCH + h * 65];
#pragma unroll
        for (int d = 0; d < DH; d++) ov[d] += pr * vp[d];
    }
    __syncthreads();
#pragma unroll
    for (int d = 0; d < DH; d++) qsm[tt * PITCH + h * 65 + d] = ov[d];
    __syncthreads();
    for (int i = tid; i < NS * DD; i += 256) {
        int r = i >> 10, hd = i & 1023;
        int hh = hd >> 6, d = hd & 63;
        out[((size_t)b * LL + t0) * DD + i] = qsm[r * PITCH + hh * 65 + d];
    }
}

// ---------------- host launch ----------------
extern "C" void kernel_launch(void* const* d_in, const int* in_sizes, int n_in,
                              void* d_out, int out_size)
{
    const float* x    = (const float*)d_in[0];
    const float* sq   = (const float*)d_in[1];
    const float* dWq  = (const float*)d_in[2];
    const float* dWk  = (const float*)d_in[3];
    const float* dWv  = (const float*)d_in[4];
    const float* dWo  = (const float*)d_in[5];
    const float* dbq  = (const float*)d_in[6];
    const float* dbk  = (const float*)d_in[7];
    const float* dbv  = (const float*)d_in[8];
    const float* dbo  = (const float*)d_in[9];
    const float* cWq  = (const float*)d_in[10];
    const float* cWk  = (const float*)d_in[11];
    const float* cWv  = (const float*)d_in[12];
    const float* cWo  = (const float*)d_in[13];
    const float* cbq  = (const float*)d_in[14];
    const float* cbk  = (const float*)d_in[15];
    const float* cbv  = (const float*)d_in[16];
    const float* cbo  = (const float*)d_in[17];
    const float* elng = (const float*)d_in[18];
    const float* elnb = (const float*)d_in[19];
    const float* eW1  = (const float*)d_in[20];
    const float* eb1  = (const float*)d_in[21];
    const float* eWg  = (const float*)d_in[22];
    const float* ebg  = (const float*)d_in[23];
    const float* eW2  = (const float*)d_in[24];
    const float* eb2  = (const float*)d_in[25];
    float* out = (float*)d_out;

    float *kh, *vh, *qh1, *att1, *o, *hn, *ug, *qh2, *kh2, *vh2, *att2;
    float *sc, *avp, *skp, *w2p;
    cudaGetSymbolAddress((void**)&kh,   g_kh);
    cudaGetSymbolAddress((void**)&vh,   g_vh);
    cudaGetSymbolAddress((void**)&qh1,  g_qh1);
    cudaGetSymbolAddress((void**)&att1, g_att1);
    cudaGetSymbolAddress((void**)&o,    g_o);
    cudaGetSymbolAddress((void**)&hn,   g_hn);
    cudaGetSymbolAddress((void**)&ug,   g_ug);
    cudaGetSymbolAddress((void**)&qh2,  g_qh2);
    cudaGetSymbolAddress((void**)&kh2,  g_kh2);
    cudaGetSymbolAddress((void**)&vh2,  g_vh2);
    cudaGetSymbolAddress((void**)&att2, g_att2);
    cudaGetSymbolAddress((void**)&sc,   g_sc);
    cudaGetSymbolAddress((void**)&avp,  g_part);
    cudaGetSymbolAddress((void**)&skp,  g_skp);
    cudaGetSymbolAddress((void**)&w2p,  g_w2p);

    const int SMEM_COMB = 3 * 16 * (HH * 65) * 4;
    cudaFuncSetAttribute(combine_attn, cudaFuncAttributeMaxDynamicSharedMemorySize, SMEM_COMB);

    dim3 gBig(DD / 128, (BB * LL) / 128);   // (8, 64)
    dim3 gSk(DD / 64, 8);                   // skinny split-K

    // dispatch projections
    gemm_tf32<<<gBig, 256>>>(x, dWk, dbk, kh, BB * LL, DD, DD);
    gemm_tf32<<<gBig, 256>>>(x, dWv, dbv, vh, BB * LL, DD, DD);
    gemm_skinny<16><<<gSk, 256>>>(sq, dWq, skp, DD, DD);
    skinny_reduce<<<(16 * DD) / 256, 256>>>(skp, dbq, qh1, 16, DD);

    // dispatch attention
    disp_scores<<<dim3(LL / 128, HH, BB), 256>>>(qh1, kh, sc);
    disp_softmax<<<BB * HH * NS, 256>>>(sc);
    disp_av<<<dim3(HH, BB, 16), 256>>>(sc, vh, avp);
    disp_reduce<<<(BB * NS * DD) / 256, 256>>>(avp, att1);

    // dispatch output projection + residual
    gemm_skinny<64><<<gSk, 256>>>(att1, dWo, skp, DD, DD);
    skinny_reduce<<<(64 * DD) / 256, 256>>>(skp, dbo, o, 64, DD);
    add_slotq<<<(BB * NS * DD) / 256, 256>>>(o, sq);

    // experts
    ln_kernel<<<BB * NS, 256>>>(o, elng, elnb, hn);
    expert_ug<<<dim3(FF / 128, EE), 128>>>(hn, eW1, eb1, eWg, ebg, ug);
    expert_w2p<<<dim3(DD / 128, EE, 8), 128>>>(ug, eW2, w2p);
    w2_reduce<<<(BB * EE * DD) / 256, 256>>>(w2p, eb2, o);

    // combine projections
    gemm_tf32<<<gBig, 256>>>(x, cWq, cbq, qh2, BB * LL, DD, DD);
    gemm_skinny<64><<<gSk, 256>>>(o, cWk, skp, DD, DD);
    skinny_reduce<<<(64 * DD) / 256, 256>>>(skp, cbk, kh2, 64, DD);
    gemm_skinny<64><<<gSk, 256>>>(o, cWv, skp, DD, DD);
    skinny_reduce<<<(64 * DD) / 256, 256>>>(skp, cbv, vh2, 64, DD);

    // combine attention + final projection
    combine_attn<<<dim3(LL / 16, BB), 256, SMEM_COMB>>>(qh2, kh2, vh2, att2);
    gemm_tf32<<<gBig, 256>>>(att2, cWo, cbo, out, BB * LL, DD, DD);
}